// round 15
// baseline (speedup 1.0000x reference)
#include <cuda_runtime.h>
#include <cstdint>

#define B_ 4096
#define T_ 120
#define I_ 64
#define H_ 128
#define G_ 384   // 3*H

// Input-side gate pre-activations, layout [B][T][G] (row = b*T + t).
// Natural gate-blocked cols g = gate*128 + j. Bias fold: b_ih (all gates)
// + b_hh (r,z ONLY — n-gate's b_hh is multiplied by r; added in K2).
__device__ float g_xg[(size_t)B_ * T_ * G_];

#define TANHA(y, x) asm("tanh.approx.f32 %0, %1;" : "=f"(y) : "f"(x))

__device__ __forceinline__ float sigmoid_mufu(float x) {
    float th; TANHA(th, 0.5f * x);
    return fmaf(0.5f, th, 0.5f);
}
__device__ __forceinline__ float tanh_mufu(float x) {
    float th; TANHA(th, x);
    return th;
}

// pack two floats -> bf16x2 (lo_ in low half, hi_ in high half)
#define PBF2(r, lo_, hi_) \
    asm("cvt.rn.bf16x2.f32 %0, %1, %2;" : "=r"(r) : "f"(hi_), "f"(lo_))

#define MMAB(acc, a0, a1, a2, a3, b0, b1)                                 \
    asm volatile("mma.sync.aligned.m16n8k16.row.col.f32.bf16.bf16.f32 "   \
        "{%0,%1,%2,%3}, {%4,%5,%6,%7}, {%8,%9}, {%0,%1,%2,%3};"           \
        : "+f"((acc)[0]), "+f"((acc)[1]), "+f"((acc)[2]), "+f"((acc)[3])  \
        : "r"(a0), "r"(a1), "r"(a2), "r"(a3), "r"(b0), "r"(b1))

// ---------------- mbarrier helpers (K2 pipeline) ----------------
__device__ __forceinline__ uint32_t elect_one() {
    uint32_t p;
    asm volatile("{\n\t.reg .pred P;\n\telect.sync _|P, 0xFFFFFFFF;\n\t"
                 "selp.b32 %0, 1, 0, P;\n\t}" : "=r"(p));
    return p;
}
__device__ __forceinline__ uint32_t s2u(const void* p) {
    uint32_t a;
    asm("{ .reg .u64 t; cvta.to.shared.u64 t, %1; cvt.u32.u64 %0, t; }"
        : "=r"(a) : "l"(p));
    return a;
}
#define MBAR_INIT(a,c) asm volatile("mbarrier.init.shared.b64 [%0], %1;" :: "r"(a), "r"(c) : "memory")
#define MBAR_ARRIVE(a) asm volatile("mbarrier.arrive.shared.b64 _, [%0];" :: "r"(a) : "memory")
#define MBAR_ARRIVE_CNT(a,n) asm volatile("mbarrier.arrive.shared.b64 _, [%0], %1;" :: "r"(a), "r"(n) : "memory")

#define MBAR_WAIT(mb, ph) do {                                               \
    uint32_t _m = (mb), _p = (ph), _d;                                       \
    asm volatile("{\n\t.reg .pred P;\n\t"                                    \
        "mbarrier.try_wait.parity.acquire.cta.shared::cta.b64 P, [%1], %2;\n\t" \
        "selp.b32 %0, 1, 0, P;\n\t}" : "=r"(_d) : "r"(_m), "r"(_p) : "memory"); \
    if (!_d) {                                                               \
        asm volatile("{\n\t.reg .pred P1;\n\t"                               \
            "WL_%=:\n\t"                                                     \
            "mbarrier.try_wait.parity.acquire.cta.shared::cta.b64 P1, [%0], %1, 0x989680;\n\t" \
            "@P1 bra.uni WD_%=;\n\t bra.uni WL_%=;\n\tWD_%=:\n\t}"           \
            :: "r"(_m), "r"(_p) : "memory");                                 \
    }                                                                        \
} while (0)

// =====================================================================
// Kernel 1 (persistent, mma.sync bf16x3, software-pipelined):
//   x_gates = x @ W_ih^T + b_ih (+ b_hh for r,z)  -> g_xg[B][T][G]
// 148 CTAs x 512 threads. (unchanged from round 13)
// =====================================================================
#define NT1 ((B_ * T_) / 64)
#define K1_GRID 148
#define K1_ITER ((NT1 + K1_GRID - 1) / K1_GRID)

#define W1_HALF 49152
#define X1_OFF  (2 * W1_HALF)
#define X1_HALF 9216
#define B1_OFF  (X1_OFF + 2 * X1_HALF)
#define K1_SMEM (B1_OFF + G_ * 4)

__global__ __launch_bounds__(512, 1) void k1_xgates(
    const float* __restrict__ x,
    const float* __restrict__ Wih,
    const float* __restrict__ bih,
    const float* __restrict__ bhh)
{
    extern __shared__ char smem[];
    const int tid  = threadIdx.x;
    const int lane = tid & 31, wid = tid >> 5;
    const int gr   = lane >> 2, tig = lane & 3;
    const int mt   = wid & 3;
    const int u    = wid >> 2;

    for (int idx = tid; idx < G_ * I_; idx += 512) {
        int n = idx >> 6, k = idx & 63;
        int nt = n >> 3, col = n & 7;
        int kt = k >> 4, kin = k & 15;
        int tg = (kin >> 1) & 3, reg = kin >> 3, half = kin & 1;
        int byte = (kt * 48 + nt) * 256 + (col * 4 + tg) * 8 + reg * 4 + half * 2;
        float w = Wih[idx];
        unsigned short hb; asm("cvt.rn.bf16.f32 %0, %1;" : "=h"(hb) : "f"(w));
        float hf = __uint_as_float((uint32_t)hb << 16);
        float rem = w - hf;
        unsigned short lb; asm("cvt.rn.bf16.f32 %0, %1;" : "=h"(lb) : "f"(rem));
        *(unsigned short*)(smem + byte)           = hb;
        *(unsigned short*)(smem + W1_HALF + byte) = lb;
    }
    {
        float* bW = (float*)(smem + B1_OFF);
        for (int g = tid; g < G_; g += 512)
            bW[g] = bih[g] + (g < 2 * H_ ? bhh[g] : 0.0f);
    }

    const char* wbh = smem + u * 12 * 256 + lane * 8;
    const char* wbl = wbh + W1_HALF;
    char* xh = smem + X1_OFF;
    const float* bI = (const float*)(smem + B1_OFF);

    float2 xr[4];
    if (blockIdx.x < NT1) {
        const size_t rn = (size_t)blockIdx.x * 64;
        #pragma unroll
        for (int j = 0; j < 4; j++) {
            int idx = tid + j * 512;
            int row = idx >> 5, kp = idx & 31;
            xr[j] = *(const float2*)(x + (rn + row) * I_ + 2 * kp);
        }
    }

    for (int it = 0; it < K1_ITER; it++) {
        const int tt = blockIdx.x + it * K1_GRID;
        if (tt >= NT1) break;
        const size_t r0 = (size_t)tt * 64;

        if (it) __syncthreads();
        #pragma unroll
        for (int j = 0; j < 4; j++) {
            int idx = tid + j * 512;
            int row = idx >> 5, kp = idx & 31;
            uint32_t whi; PBF2(whi, xr[j].x, xr[j].y);
            float v0r = __uint_as_float(whi << 16);
            float v1r = __uint_as_float(whi & 0xffff0000u);
            uint32_t wlo; PBF2(wlo, xr[j].x - v0r, xr[j].y - v1r);
            int w = (row * 36 + kp) * 4;
            *(uint32_t*)(xh + w)           = whi;
            *(uint32_t*)(xh + X1_HALF + w) = wlo;
        }
        __syncthreads();

        const int ttn = tt + K1_GRID;
        if (ttn < NT1) {
            const size_t rn = (size_t)ttn * 64;
            #pragma unroll
            for (int j = 0; j < 4; j++) {
                int idx = tid + j * 512;
                int row = idx >> 5, kp = idx & 31;
                xr[j] = *(const float2*)(x + (rn + row) * I_ + 2 * kp);
            }
        }

        float acc[12][4];
        #pragma unroll
        for (int nt = 0; nt < 12; nt++)
            #pragma unroll
            for (int d = 0; d < 4; d++) acc[nt][d] = 0.0f;

        #pragma unroll
        for (int kt = 0; kt < 4; kt++) {
            const char* ha = xh + ((mt * 16 + gr) * 36 + kt * 8 + tig) * 4;
            uint32_t ah0 = *(const uint32_t*)(ha);
            uint32_t ah1 = *(const uint32_t*)(ha + 8 * 144);
            uint32_t ah2 = *(const uint32_t*)(ha + 16);
            uint32_t ah3 = *(const uint32_t*)(ha + 8 * 144 + 16);
            const char* hl = ha + X1_HALF;
            uint32_t al0 = *(const uint32_t*)(hl);
            uint32_t al1 = *(const uint32_t*)(hl + 8 * 144);
            uint32_t al2 = *(const uint32_t*)(hl + 16);
            uint32_t al3 = *(const uint32_t*)(hl + 8 * 144 + 16);

            const char* wkh = wbh + kt * 48 * 256;
            const char* wkl = wbl + kt * 48 * 256;
            #pragma unroll
            for (int nt = 0; nt < 12; nt++) {
                uint2 bh = *(const uint2*)(wkh + nt * 256);
                uint2 bl = *(const uint2*)(wkl + nt * 256);
                MMAB(acc[nt], ah0, ah1, ah2, ah3, bh.x, bh.y);
                MMAB(acc[nt], al0, al1, al2, al3, bh.x, bh.y);
                MMAB(acc[nt], ah0, ah1, ah2, ah3, bl.x, bl.y);
            }
        }

        {
            const size_t ra = r0 + mt * 16 + gr;
            float* da = g_xg + ra * G_ + u * 96 + 2 * tig;
            float* db = da + (size_t)8 * G_;
            #pragma unroll
            for (int nt = 0; nt < 12; nt++) {
                float2 bi = *(const float2*)(bI + u * 96 + nt * 8 + 2 * tig);
                *(float2*)(da + nt * 8) =
                    make_float2(acc[nt][0] + bi.x, acc[nt][1] + bi.y);
                *(float2*)(db + nt * 8) =
                    make_float2(acc[nt][2] + bi.x, acc[nt][3] + bi.y);
            }
        }
    }
}

// =====================================================================
// Kernel 2 (mma.sync bf16x3, mbarrier pipeline): recurrence.
// 128 CTAs x 512 threads, 32 batch rows/CTA. Warp (mt 0..1, u 0..7).
// Full __syncthreads replaced by producer/consumer mbarriers:
//   FL/FH (count 8): h lo/hi half ready for step t (wait parity t&1)
//   E0/E1 (count 16): h buffer free to overwrite (wait parity (t>>1)&1)
// =====================================================================
#define WPK_HALF 98304
#define HB_OFF   (2 * WPK_HALF)
#define HB_SPLIT 8704
#define HB_BUF   (2 * HB_SPLIT)
#define MB_OFF   (HB_OFF + 2 * HB_BUF)     // 231424
#define K2M_SMEM (MB_OFF + 32)             // 231456

__global__ __launch_bounds__(512, 1) void k2_recur_mma(
    const float* __restrict__ Whh,
    const float* __restrict__ bhh,
    float* __restrict__ out,      // [B, T, H]
    float* __restrict__ hT_out)   // [B, H]
{
    extern __shared__ char smem[];
    const uint32_t sb  = s2u(smem);
    const uint32_t mFL = sb + MB_OFF;
    const uint32_t mFH = mFL + 8;
    const uint32_t mE0 = mFL + 16;
    const uint32_t mE1 = mFL + 24;

    const int tid  = threadIdx.x;
    const int lane = tid & 31, wid = tid >> 5;
    const int gr   = lane >> 2, tig = lane & 3;
    const int mt   = wid & 1;                 // row block (16 rows)
    const int u    = wid >> 1;                // unit block (16 units), 0..7
    const size_t b0r = (size_t)blockIdx.x * 32;
    const uint32_t myF = (u < 4) ? mFL : mFH;

    // W_hh -> bf16 hi/lo fragment tiles
    for (int idx = tid; idx < G_ * H_; idx += 512) {
        int n = idx >> 7, k = idx & 127;
        int gg = n >> 7, j = n & 127;
        int uu = j >> 5, nt = (j >> 3) & 3, col = j & 7;
        int kt = k >> 4, kin = k & 15;
        int tg = (kin >> 1) & 3, reg = kin >> 3, half = kin & 1;
        int TI = ((kt * 4 + uu) * 3 + gg) * 4 + nt;
        int byte = TI * 256 + (col * 4 + tg) * 8 + reg * 4 + half * 2;
        float w = Whh[idx];
        unsigned short hb; asm("cvt.rn.bf16.f32 %0, %1;" : "=h"(hb) : "f"(w));
        float hf = __uint_as_float((uint32_t)hb << 16);
        float rem = w - hf;
        unsigned short lb; asm("cvt.rn.bf16.f32 %0, %1;" : "=h"(lb) : "f"(rem));
        *(unsigned short*)(smem + byte)            = hb;
        *(unsigned short*)(smem + WPK_HALF + byte) = lb;
    }
    for (int i = tid; i < HB_BUF / 4; i += 512)
        *(uint32_t*)(smem + HB_OFF + 4 * i) = 0u;     // h_0 = 0 (buffer 0)
    if (tid == 0) {
        MBAR_INIT(mFL, 8);
        MBAR_INIT(mFH, 8);
        MBAR_INIT(mE0, 16);
        MBAR_INIT(mE1, 16);
    }
    __syncthreads();
    if (tid == 0) {        // priming: h_0 "full" (both halves), buffer 1 "empty"
        MBAR_ARRIVE_CNT(mFL, 8);
        MBAR_ARRIVE_CNT(mFH, 8);
        MBAR_ARRIVE_CNT(mE1, 16);
    }

    const char* wbh = smem + (u >> 1) * 12 * 256 + (u & 1) * 512 + lane * 8;
    const char* wbl = wbh + WPK_HALF;

    float2 bn[2];
    #pragma unroll
    for (int nt = 0; nt < 2; nt++)
        bn[nt] = *(const float2*)(bhh + 2 * H_ + u * 16 + nt * 8 + 2 * tig);

    float hprev[2][4];
    #pragma unroll
    for (int nt = 0; nt < 2; nt++)
        #pragma unroll
        for (int d = 0; d < 4; d++) hprev[nt][d] = 0.0f;

    const int r0 = mt * 16 + gr;

    for (int t = 0; t < T_; t++) {
        const uint32_t p = (uint32_t)(t & 1);
        const char* hb  = smem + HB_OFF + p * HB_BUF;
        char* hbn = (char*)smem + HB_OFF + (p ^ 1) * HB_BUF;

        // x-gates (t-dependent only — issue before waiting on h)
        float2 xf[2][3][2];
        {
            const float* xgp = g_xg + ((b0r + r0) * (size_t)T_ + t) * G_
                               + u * 16 + 2 * tig;
            #pragma unroll
            for (int rh = 0; rh < 2; rh++)
                #pragma unroll
                for (int gg = 0; gg < 3; gg++)
                    #pragma unroll
                    for (int nt = 0; nt < 2; nt++)
                        xf[rh][gg][nt] = *(const float2*)
                            (xgp + (size_t)rh * 8 * T_ * G_ + gg * 128 + nt * 8);
        }

        float acc[3][2][4];
        #pragma unroll
        for (int gg = 0; gg < 3; gg++)
            #pragma unroll
            for (int nt = 0; nt < 2; nt++)
                #pragma unroll
                for (int d = 0; d < 4; d++) acc[gg][nt][d] = 0.0f;

        MBAR_WAIT(mFL, p);   // h units 0..63 ready (k for kt 0..3)
        #pragma unroll
        for (int kt = 0; kt < 4; kt++) {
            const char* ha = hb + r0 * 272 + (kt * 8 + tig) * 4;
            uint32_t ah0 = *(const uint32_t*)(ha);
            uint32_t ah1 = *(const uint32_t*)(ha + 8 * 272);
            uint32_t ah2 = *(const uint32_t*)(ha + 16);
            uint32_t ah3 = *(const uint32_t*)(ha + 8 * 272 + 16);
            const char* hl = ha + HB_SPLIT;
            uint32_t al0 = *(const uint32_t*)(hl);
            uint32_t al1 = *(const uint32_t*)(hl + 8 * 272);
            uint32_t al2 = *(const uint32_t*)(hl + 16);
            uint32_t al3 = *(const uint32_t*)(hl + 8 * 272 + 16);

            const char* wkh = wbh + kt * 12288;
            const char* wkl = wbl + kt * 12288;
            #pragma unroll
            for (int gg = 0; gg < 3; gg++) {
                #pragma unroll
                for (int nt = 0; nt < 2; nt++) {
                    uint2 bh = *(const uint2*)(wkh + gg * 1024 + nt * 256);
                    uint2 bl = *(const uint2*)(wkl + gg * 1024 + nt * 256);
                    MMAB(acc[gg][nt], ah0, ah1, ah2, ah3, bh.x, bh.y);
                    MMAB(acc[gg][nt], al0, al1, al2, al3, bh.x, bh.y);
                    MMAB(acc[gg][nt], ah0, ah1, ah2, ah3, bl.x, bl.y);
                }
            }
        }

        MBAR_WAIT(mFH, p);   // h units 64..127 ready
        #pragma unroll
        for (int kt = 4; kt < 8; kt++) {
            const char* ha = hb + r0 * 272 + (kt * 8 + tig) * 4;
            uint32_t ah0 = *(const uint32_t*)(ha);
            uint32_t ah1 = *(const uint32_t*)(ha + 8 * 272);
            uint32_t ah2 = *(const uint32_t*)(ha + 16);
            uint32_t ah3 = *(const uint32_t*)(ha + 8 * 272 + 16);
            const char* hl = ha + HB_SPLIT;
            uint32_t al0 = *(const uint32_t*)(hl);
            uint32_t al1 = *(const uint32_t*)(hl + 8 * 272);
            uint32_t al2 = *(const uint32_t*)(hl + 16);
            uint32_t al3 = *(const uint32_t*)(hl + 8 * 272 + 16);

            const char* wkh = wbh + kt * 12288;
            const char* wkl = wbl + kt * 12288;
            #pragma unroll
            for (int gg = 0; gg < 3; gg++) {
                #pragma unroll
                for (int nt = 0; nt < 2; nt++) {
                    uint2 bh = *(const uint2*)(wkh + gg * 1024 + nt * 256);
                    uint2 bl = *(const uint2*)(wkl + gg * 1024 + nt * 256);
                    MMAB(acc[gg][nt], ah0, ah1, ah2, ah3, bh.x, bh.y);
                    MMAB(acc[gg][nt], al0, al1, al2, al3, bh.x, bh.y);
                    MMAB(acc[gg][nt], ah0, ah1, ah2, ah3, bl.x, bl.y);
                }
            }
        }

        // this warp is done reading buffer p
        if (elect_one()) MBAR_ARRIVE(p ? mE1 : mE0);

        // elementwise GRU update (registers only)
        uint32_t whi_r[2][2], wlo_r[2][2];
        #pragma unroll
        for (int nt = 0; nt < 2; nt++) {
            #pragma unroll
            for (int rh = 0; rh < 2; rh++) {
                float h2[2];
                #pragma unroll
                for (int cc = 0; cc < 2; cc++) {
                    int d = rh * 2 + cc;
                    float xr = cc ? xf[rh][0][nt].y : xf[rh][0][nt].x;
                    float xz = cc ? xf[rh][1][nt].y : xf[rh][1][nt].x;
                    float xn = cc ? xf[rh][2][nt].y : xf[rh][2][nt].x;
                    float bnv = cc ? bn[nt].y : bn[nt].x;
                    float r = sigmoid_mufu(xr + acc[0][nt][d]);
                    float z = sigmoid_mufu(xz + acc[1][nt][d]);
                    float n = tanh_mufu(xn + r * (acc[2][nt][d] + bnv));
                    float h = n + z * (hprev[nt][d] - n);
                    hprev[nt][d] = h;
                    h2[cc] = h;
                }
                uint32_t whi; PBF2(whi, h2[0], h2[1]);
                float h0r = __uint_as_float(whi << 16);
                float h1r = __uint_as_float(whi & 0xffff0000u);
                uint32_t wlo; PBF2(wlo, h2[0] - h0r, h2[1] - h1r);
                whi_r[nt][rh] = whi;
                wlo_r[nt][rh] = wlo;
            }
        }

        // wait for write buffer (p^1) to be free, then publish h_{t+1}
        MBAR_WAIT(p ? mE0 : mE1, (uint32_t)((t >> 1) & 1));
        #pragma unroll
        for (int nt = 0; nt < 2; nt++) {
            #pragma unroll
            for (int rh = 0; rh < 2; rh++) {
                int row = r0 + rh * 8;
                char* hw = hbn + row * 272 + (u * 8 + nt * 4 + tig) * 4;
                *(uint32_t*)hw = whi_r[nt][rh];
                *(uint32_t*)(hw + HB_SPLIT) = wlo_r[nt][rh];
            }
        }
        if (elect_one()) MBAR_ARRIVE(myF);   // my half of h_{t+1} ready

        // out-stores off the critical path
        #pragma unroll
        for (int nt = 0; nt < 2; nt++)
            #pragma unroll
            for (int rh = 0; rh < 2; rh++)
                *(float2*)(out + (b0r + r0 + rh * 8) * (size_t)(T_ * H_)
                           + (size_t)t * H_ + u * 16 + nt * 8 + 2 * tig) =
                    make_float2(hprev[nt][rh * 2], hprev[nt][rh * 2 + 1]);
    }

    #pragma unroll
    for (int nt = 0; nt < 2; nt++)
        #pragma unroll
        for (int rh = 0; rh < 2; rh++)
            *(float2*)(hT_out + (b0r + r0 + rh * 8) * H_
                       + u * 16 + nt * 8 + 2 * tig) =
                make_float2(hprev[nt][rh * 2], hprev[nt][rh * 2 + 1]);
}

extern "C" void kernel_launch(void* const* d_in, const int* in_sizes, int n_in,
                              void* d_out, int out_size)
{
    const float* x   = (const float*)d_in[0];
    const float* Wih = (const float*)d_in[1];
    const float* Whh = (const float*)d_in[2];
    const float* bih = (const float*)d_in[3];
    const float* bhh = (const float*)d_in[4];

    float* out = (float*)d_out;                       // [B, T, H]
    float* hT  = out + (size_t)B_ * T_ * H_;          // [B, H]

    cudaFuncSetAttribute(k1_xgates,    cudaFuncAttributeMaxDynamicSharedMemorySize, K1_SMEM);
    cudaFuncSetAttribute(k2_recur_mma, cudaFuncAttributeMaxDynamicSharedMemorySize, K2M_SMEM);

    k1_xgates<<<K1_GRID, 512, K1_SMEM>>>(x, Wih, bih, bhh);
    k2_recur_mma<<<B_ / 32, 512, K2M_SMEM>>>(Whh, bhh, out, hT);
}